// round 6
// baseline (speedup 1.0000x reference)
#include <cuda_runtime.h>
#include <cuda_fp16.h>

#define PP 4
#define NN 65536
#define DD 128
#define OO 128
#define EE 500000
#define MM 32768
#define TOTAL_ROWS 655360   // 4*N + 12*M
#define NEDGES (16 * EE)    // 8,000,000

#define BM 128
#define BN 128
#define BK 32
#define AS_STRIDE 36
#define BS_STRIDE 136

// ---------------- scratch (static device arrays; no allocation) ----------------
__device__ __half g_FN[(size_t)PP * NN * OO];        // feats @ W_neigh, fp16 (67 MB)
__device__ __half g_SelfM[(size_t)PP * MM * OO];     // (feats@W_self + b) rows [0,M), fp16 (33 MB)
__device__ int   g_cnt[TOTAL_ROWS];
__device__ int   g_off[TOTAL_ROWS];
__device__ int   g_cur[TOTAL_ROWS];
__device__ int   g_part[1024];
__device__ int   g_sorted_src[NEDGES];               // edge src ids sorted by dst row (32 MB)

__constant__ int c_blkoff[17] = {
    0,      65536,  98304,  131072,
    163840, 196608, 262144, 294912,
    327680, 360448, 393216, 458752,
    491520, 524288, 557056, 589824, 655360};

__device__ __forceinline__ unsigned f2tf32(float v) {
    unsigned r;
    asm("cvt.rna.tf32.f32 %0, %1;" : "=r"(r) : "f"(v));
    return r;
}

// ---------------- Phase A: tf32 tensor-core GEMM ----------------
__global__ __launch_bounds__(256, 2) void gemm_self_fn(
    const float* __restrict__ feats, const float* __restrict__ Ws,
    const float* __restrict__ Wn, const float* __restrict__ bias,
    float* __restrict__ out)
{
    __shared__ unsigned As[BM][AS_STRIDE];
    __shared__ unsigned Bs[BK][BS_STRIDE];

    const int s    = blockIdx.z;
    const int row0 = blockIdx.x * BM;
    const bool isSelf = (blockIdx.y == 0);
    const float* A = feats + (size_t)s * NN * DD;
    const float* B = (isSelf ? Ws : Wn) + (size_t)s * DD * OO;

    const int t    = threadIdx.x;
    const int lane = t & 31;
    const int wid  = t >> 5;
    const int wm   = wid >> 1;
    const int wn   = wid & 1;

    float C[2][8][4];
#pragma unroll
    for (int mf = 0; mf < 2; mf++)
#pragma unroll
        for (int j = 0; j < 8; j++)
#pragma unroll
            for (int q = 0; q < 4; q++) C[mf][j][q] = 0.0f;

    for (int kt = 0; kt < DD; kt += BK) {
#pragma unroll
        for (int q = 0; q < 4; q++) {
            int i  = t + 256 * q;
            int r  = i >> 3;
            int k0 = (i & 7) * 4;
            float4 v = *(const float4*)(A + (size_t)(row0 + r) * DD + kt + k0);
            uint4 u = make_uint4(f2tf32(v.x), f2tf32(v.y), f2tf32(v.z), f2tf32(v.w));
            *(uint4*)&As[r][k0] = u;
        }
#pragma unroll
        for (int q = 0; q < 4; q++) {
            int i  = t + 256 * q;
            int k  = i >> 5;
            int n0 = (i & 31) * 4;
            float4 v = *(const float4*)(B + (size_t)(kt + k) * OO + n0);
            uint4 u = make_uint4(f2tf32(v.x), f2tf32(v.y), f2tf32(v.z), f2tf32(v.w));
            *(uint4*)&Bs[k][n0] = u;
        }
        __syncthreads();

#pragma unroll
        for (int kk = 0; kk < BK; kk += 8) {
            unsigned a[2][4];
#pragma unroll
            for (int mf = 0; mf < 2; mf++) {
                int r = wm * 32 + mf * 16 + (lane >> 2);
                int kc = kk + (lane & 3);
                a[mf][0] = As[r][kc];
                a[mf][1] = As[r + 8][kc];
                a[mf][2] = As[r][kc + 4];
                a[mf][3] = As[r + 8][kc + 4];
            }
#pragma unroll
            for (int j = 0; j < 8; j++) {
                int n = wn * 64 + j * 8 + (lane >> 2);
                unsigned b0 = Bs[kk + (lane & 3)][n];
                unsigned b1 = Bs[kk + (lane & 3) + 4][n];
#pragma unroll
                for (int mf = 0; mf < 2; mf++) {
                    asm("mma.sync.aligned.m16n8k8.row.col.f32.tf32.tf32.f32 "
                        "{%0,%1,%2,%3}, {%4,%5,%6,%7}, {%8,%9}, {%0,%1,%2,%3};"
                        : "+f"(C[mf][j][0]), "+f"(C[mf][j][1]),
                          "+f"(C[mf][j][2]), "+f"(C[mf][j][3])
                        : "r"(a[mf][0]), "r"(a[mf][1]), "r"(a[mf][2]), "r"(a[mf][3]),
                          "r"(b0), "r"(b1));
                }
            }
        }
        __syncthreads();
    }

    const int col0 = wn * 64;
    if (isSelf) {
#pragma unroll
        for (int mf = 0; mf < 2; mf++) {
            int r0 = row0 + wm * 32 + mf * 16 + (lane >> 2);
#pragma unroll
            for (int j = 0; j < 8; j++) {
                int c = col0 + j * 8 + (lane & 3) * 2;
                float b0v = __ldg(bias + s * OO + c);
                float b1v = __ldg(bias + s * OO + c + 1);
                float2 v0 = make_float2(C[mf][j][0] + b0v, C[mf][j][1] + b1v);
                float2 v1 = make_float2(C[mf][j][2] + b0v, C[mf][j][3] + b1v);
                *(float2*)(out + ((size_t)s * NN + r0) * OO + c)     = v0;
                *(float2*)(out + ((size_t)s * NN + r0 + 8) * OO + c) = v1;
                if (r0 < MM) {
                    *(__half2*)(g_SelfM + ((size_t)s * MM + r0) * OO + c)
                        = __floats2half2_rn(v0.x, v0.y);
                    *(__half2*)(g_SelfM + ((size_t)s * MM + r0 + 8) * OO + c)
                        = __floats2half2_rn(v1.x, v1.y);
                }
            }
        }
    } else {
#pragma unroll
        for (int mf = 0; mf < 2; mf++) {
            int r0 = row0 + wm * 32 + mf * 16 + (lane >> 2);
#pragma unroll
            for (int j = 0; j < 8; j++) {
                int c = col0 + j * 8 + (lane & 3) * 2;
                __half2 h0 = __floats2half2_rn(C[mf][j][0], C[mf][j][1]);
                __half2 h1 = __floats2half2_rn(C[mf][j][2], C[mf][j][3]);
                *(__half2*)(g_FN + ((size_t)s * NN + r0) * OO + c)     = h0;
                *(__half2*)(g_FN + ((size_t)s * NN + r0 + 8) * OO + c) = h1;
            }
        }
    }
}

// ---------------- Sort pipeline ----------------
__global__ __launch_bounds__(256) void hist_kernel(const int* __restrict__ e_dst)
{
    int e = blockIdx.x * 256 + threadIdx.x;
    int blk = e / EE;
    int row = c_blkoff[blk] + __ldg(e_dst + e);
    atomicAdd(&g_cnt[row], 1);
}

__global__ __launch_bounds__(1024) void scan1_kernel()
{
    __shared__ int sm[1024];
    int tid = threadIdx.x;
    int i = blockIdx.x * 1024 + tid;
    int v = g_cnt[i];
    sm[tid] = v;
    __syncthreads();
    for (int ofs = 1; ofs < 1024; ofs <<= 1) {
        int t = (tid >= ofs) ? sm[tid - ofs] : 0;
        __syncthreads();
        sm[tid] += t;
        __syncthreads();
    }
    g_off[i] = sm[tid] - v;
    if (tid == 1023) g_part[blockIdx.x] = sm[1023];
}

__global__ __launch_bounds__(1024) void scan2_kernel()
{
    __shared__ int sm[1024];
    int tid = threadIdx.x;
    int v = (tid < 640) ? g_part[tid] : 0;
    sm[tid] = v;
    __syncthreads();
    for (int ofs = 1; ofs < 1024; ofs <<= 1) {
        int t = (tid >= ofs) ? sm[tid - ofs] : 0;
        __syncthreads();
        sm[tid] += t;
        __syncthreads();
    }
    if (tid < 640) g_part[tid] = sm[tid] - v;
}

__global__ __launch_bounds__(1024) void scan3_kernel()
{
    int i = blockIdx.x * 1024 + threadIdx.x;
    int o = g_off[i] + g_part[blockIdx.x];
    g_off[i] = o;
    g_cur[i] = o;
}

__global__ __launch_bounds__(256) void scatter_kernel(
    const int* __restrict__ e_src, const int* __restrict__ e_dst)
{
    int e = blockIdx.x * 256 + threadIdx.x;
    int blk = e / EE;
    int row = c_blkoff[blk] + __ldg(e_dst + e);
    int pos = atomicAdd(&g_cur[row], 1);
    g_sorted_src[pos] = __ldg(e_src + e);
}

// ---------------- Phase B+C fused: warp per destination row, fp16 gather, MLP=4 ----------------
__device__ __forceinline__ void acc_add(float4& acc, uint2 raw) {
    float2 f0 = __half22float2(*(__half2*)&raw.x);
    float2 f1 = __half22float2(*(__half2*)&raw.y);
    acc.x += f0.x; acc.y += f0.y; acc.z += f1.x; acc.w += f1.y;
}

__global__ __launch_bounds__(256) void agg_combine(
    float* __restrict__ out, const int* __restrict__ merge)
{
    const int lane = threadIdx.x & 31;
    const int r = blockIdx.x * 8 + (threadIdx.x >> 5);

    int blk = 0;
#pragma unroll
    for (int k = 1; k < 16; k++)
        if (r >= c_blkoff[k]) blk = k;
    const int s = blk >> 2, d = blk & 3;
    const int lrow = r - c_blkoff[blk];

    const int base = g_off[r];
    const int deg  = g_cnt[r];
    const uint2* FNs = (const uint2*)(g_FN + (size_t)s * NN * OO);

    float4 acc = make_float4(0.f, 0.f, 0.f, 0.f);
    for (int i0 = 0; i0 < deg; i0 += 32) {
        int mi = i0 + lane;
        int msrc = (mi < deg) ? __ldg(g_sorted_src + base + mi) : 0;
        int cnt = min(32, deg - i0);
        int j = 0;
        for (; j + 4 <= cnt; j += 4) {
            int s0 = __shfl_sync(0xffffffffu, msrc, j);
            int s1 = __shfl_sync(0xffffffffu, msrc, j + 1);
            int s2 = __shfl_sync(0xffffffffu, msrc, j + 2);
            int s3 = __shfl_sync(0xffffffffu, msrc, j + 3);
            uint2 r0 = __ldg(FNs + (size_t)s0 * 32 + lane);
            uint2 r1 = __ldg(FNs + (size_t)s1 * 32 + lane);
            uint2 r2 = __ldg(FNs + (size_t)s2 * 32 + lane);
            uint2 r3 = __ldg(FNs + (size_t)s3 * 32 + lane);
            acc_add(acc, r0); acc_add(acc, r1);
            acc_add(acc, r2); acc_add(acc, r3);
        }
        for (; j < cnt; j++) {
            int sj = __shfl_sync(0xffffffffu, msrc, j);
            uint2 rj = __ldg(FNs + (size_t)sj * 32 + lane);
            acc_add(acc, rj);
        }
    }

    const float invd = (deg > 0) ? (1.0f / (float)deg) : 0.0f;

    if (s == d) {
        if (deg == 0) return;
        float* op = out + ((size_t)d * NN + lrow) * OO + lane * 4;
        asm volatile("red.global.add.v4.f32 [%0], {%1,%2,%3,%4};"
                     :: "l"(op), "f"(acc.x * invd), "f"(acc.y * invd),
                        "f"(acc.z * invd), "f"(acc.w * invd) : "memory");
    } else {
        uint2 smr = *((const uint2*)(g_SelfM + ((size_t)s * MM + lrow) * OO) + lane);
        float2 s0 = __half22float2(*(__half2*)&smr.x);
        float2 s1 = __half22float2(*(__half2*)&smr.y);
        float4 v;
        v.x = fmaf(acc.x, invd, s0.x);
        v.y = fmaf(acc.y, invd, s0.y);
        v.z = fmaf(acc.z, invd, s1.x);
        v.w = fmaf(acc.w, invd, s1.y);
        int tgt = __ldg(merge + (size_t)blk * MM + lrow);
        float* op = out + ((size_t)d * NN + tgt) * OO + lane * 4;
        asm volatile("red.global.add.v4.f32 [%0], {%1,%2,%3,%4};"
                     :: "l"(op), "f"(v.x), "f"(v.y), "f"(v.z), "f"(v.w) : "memory");
    }
}

// ---------------- launch ----------------
extern "C" void kernel_launch(void* const* d_in, const int* in_sizes, int n_in,
                              void* d_out, int out_size)
{
    const float* feats  = (const float*)d_in[0];   // [P,N,D]
    const float* Wself  = (const float*)d_in[1];   // [P,D,O]
    const float* Wneigh = (const float*)d_in[2];   // [P,D,O]
    const float* bias   = (const float*)d_in[3];   // [P,O]
    const int*   e_src  = (const int*)d_in[4];     // [P,P,E]
    const int*   e_dst  = (const int*)d_in[5];     // [P,P,E]
    const int*   merge  = (const int*)d_in[6];     // [P,P,M]
    float* out = (float*)d_out;                    // [P,N,O]

    void* cntPtr = nullptr; cudaGetSymbolAddress(&cntPtr, g_cnt);
    cudaMemsetAsync(cntPtr, 0, sizeof(int) * (size_t)TOTAL_ROWS, 0);

    hist_kernel<<<NEDGES / 256, 256>>>(e_dst);
    scan1_kernel<<<TOTAL_ROWS / 1024, 1024>>>();
    scan2_kernel<<<1, 1024>>>();
    scan3_kernel<<<TOTAL_ROWS / 1024, 1024>>>();

    gemm_self_fn<<<dim3(NN / BM, 2, PP), 256>>>(feats, Wself, Wneigh, bias, out);

    scatter_kernel<<<NEDGES / 256, 256>>>(e_src, e_dst);

    agg_combine<<<TOTAL_ROWS / 8, 256>>>(out, merge);
}

// round 7
// speedup vs baseline: 1.0246x; 1.0246x over previous
#include <cuda_runtime.h>
#include <cuda_fp16.h>

#define PP 4
#define NN 65536
#define DD 128
#define OO 128
#define EE 500000
#define MM 32768
#define TOTAL_ROWS 655360   // 4*N + 12*M
#define NEDGES (16 * EE)    // 8,000,000

#define BM 128
#define BK 32
#define AS_STRIDE 36
#define BS_STRIDE 136

#define GEMM_TILES 4096       // 512 x-tiles * 2 (self/neigh) * 4 partitions
#define SCAT_BLKS  2048
#define F2_GRID    6144       // 3 * 2048, pattern [g,g,s]

// ---------------- scratch ----------------
__device__ __half g_FN[(size_t)PP * NN * OO];        // feats @ W_neigh, fp16 (67 MB)
__device__ __half g_SelfM[(size_t)PP * MM * OO];     // (feats@W_self + b) rows [0,M), fp16 (33 MB)
__device__ int   g_cnt[TOTAL_ROWS];
__device__ int   g_off[TOTAL_ROWS];
__device__ int   g_cur[TOTAL_ROWS];
__device__ int   g_part[1024];
__device__ int   g_sorted_src[NEDGES];

__constant__ int c_blkoff[17] = {
    0,      65536,  98304,  131072,
    163840, 196608, 262144, 294912,
    327680, 360448, 393216, 458752,
    491520, 524288, 557056, 589824, 655360};

__device__ __forceinline__ unsigned f2tf32(float v) {
    unsigned r;
    asm("cvt.rna.tf32.f32 %0, %1;" : "=r"(r) : "f"(v));
    return r;
}

// ---------------- GEMM tile worker (software-pipelined, tf32 MMA) ----------------
__device__ __forceinline__ void gemm_tile(
    int tileId,
    const float* __restrict__ feats, const float* __restrict__ Ws,
    const float* __restrict__ Wn, const float* __restrict__ bias,
    float* __restrict__ out,
    unsigned (*As)[AS_STRIDE], unsigned (*Bs)[BS_STRIDE])
{
    const int x  = tileId & 511;
    const int yz = tileId >> 9;
    const bool isSelf = (yz & 1) == 0;
    const int s  = yz >> 1;
    const int row0 = x * BM;

    const float* A = feats + (size_t)s * NN * DD;
    const float* B = (isSelf ? Ws : Wn) + (size_t)s * DD * OO;

    const int t    = threadIdx.x;
    const int lane = t & 31;
    const int wid  = t >> 5;
    const int wm   = wid >> 1;
    const int wn   = wid & 1;

    float C[2][8][4];
#pragma unroll
    for (int mf = 0; mf < 2; mf++)
#pragma unroll
        for (int j = 0; j < 8; j++)
#pragma unroll
            for (int q = 0; q < 4; q++) C[mf][j][q] = 0.0f;

    float4 ra[4], rb[4];
    // stage loads for a k-tile into registers
#define LOAD_TILE(KT)                                                          \
    {                                                                          \
        _Pragma("unroll")                                                      \
        for (int q = 0; q < 4; q++) {                                          \
            int i  = t + 256 * q;                                              \
            int r  = i >> 3;                                                   \
            int k0 = (i & 7) * 4;                                              \
            ra[q] = *(const float4*)(A + (size_t)(row0 + r) * DD + (KT) + k0); \
        }                                                                      \
        _Pragma("unroll")                                                      \
        for (int q = 0; q < 4; q++) {                                          \
            int i  = t + 256 * q;                                              \
            int k  = i >> 5;                                                   \
            int n0 = (i & 31) * 4;                                             \
            rb[q] = *(const float4*)(B + (size_t)((KT) + k) * OO + n0);        \
        }                                                                      \
    }

#define STORE_TILE()                                                           \
    {                                                                          \
        _Pragma("unroll")                                                      \
        for (int q = 0; q < 4; q++) {                                          \
            int i  = t + 256 * q;                                              \
            int r  = i >> 3;                                                   \
            int k0 = (i & 7) * 4;                                              \
            *(uint4*)&As[r][k0] = make_uint4(f2tf32(ra[q].x), f2tf32(ra[q].y), \
                                             f2tf32(ra[q].z), f2tf32(ra[q].w));\
        }                                                                      \
        _Pragma("unroll")                                                      \
        for (int q = 0; q < 4; q++) {                                          \
            int i  = t + 256 * q;                                              \
            int k  = i >> 5;                                                   \
            int n0 = (i & 31) * 4;                                             \
            *(uint4*)&Bs[k][n0] = make_uint4(f2tf32(rb[q].x), f2tf32(rb[q].y), \
                                             f2tf32(rb[q].z), f2tf32(rb[q].w));\
        }                                                                      \
    }

#define COMPUTE_TILE()                                                         \
    {                                                                          \
        _Pragma("unroll")                                                      \
        for (int kk = 0; kk < BK; kk += 8) {                                   \
            unsigned a[2][4];                                                  \
            _Pragma("unroll")                                                  \
            for (int mf = 0; mf < 2; mf++) {                                   \
                int r = wm * 32 + mf * 16 + (lane >> 2);                       \
                int kc = kk + (lane & 3);                                      \
                a[mf][0] = As[r][kc];                                          \
                a[mf][1] = As[r + 8][kc];                                      \
                a[mf][2] = As[r][kc + 4];                                      \
                a[mf][3] = As[r + 8][kc + 4];                                  \
            }                                                                  \
            _Pragma("unroll")                                                  \
            for (int j = 0; j < 8; j++) {                                      \
                int n = wn * 64 + j * 8 + (lane >> 2);                         \
                unsigned b0 = Bs[kk + (lane & 3)][n];                          \
                unsigned b1 = Bs[kk + (lane & 3) + 4][n];                      \
                _Pragma("unroll")                                              \
                for (int mf = 0; mf < 2; mf++) {                               \
                    asm("mma.sync.aligned.m16n8k8.row.col.f32.tf32.tf32.f32 "  \
                        "{%0,%1,%2,%3}, {%4,%5,%6,%7}, {%8,%9}, {%0,%1,%2,%3};"\
                        : "+f"(C[mf][j][0]), "+f"(C[mf][j][1]),                \
                          "+f"(C[mf][j][2]), "+f"(C[mf][j][3])                 \
                        : "r"(a[mf][0]), "r"(a[mf][1]),                        \
                          "r"(a[mf][2]), "r"(a[mf][3]),                        \
                          "r"(b0), "r"(b1));                                   \
                }                                                              \
            }                                                                  \
        }                                                                      \
    }

    LOAD_TILE(0);
    STORE_TILE();
    __syncthreads();
#pragma unroll
    for (int kt = BK; kt < DD; kt += BK) {
        LOAD_TILE(kt);          // prefetch next tile (LDGs overlap compute)
        COMPUTE_TILE();
        __syncthreads();
        STORE_TILE();
        __syncthreads();
    }
    COMPUTE_TILE();

    // ---------------- epilogue ----------------
    const int col0 = wn * 64;
    if (isSelf) {
#pragma unroll
        for (int mf = 0; mf < 2; mf++) {
            int r0 = row0 + wm * 32 + mf * 16 + (lane >> 2);
#pragma unroll
            for (int j = 0; j < 8; j++) {
                int c = col0 + j * 8 + (lane & 3) * 2;
                float b0v = __ldg(bias + s * OO + c);
                float b1v = __ldg(bias + s * OO + c + 1);
                float2 v0 = make_float2(C[mf][j][0] + b0v, C[mf][j][1] + b1v);
                float2 v1 = make_float2(C[mf][j][2] + b0v, C[mf][j][3] + b1v);
                *(float2*)(out + ((size_t)s * NN + r0) * OO + c)     = v0;
                *(float2*)(out + ((size_t)s * NN + r0 + 8) * OO + c) = v1;
                if (r0 < MM) {
                    *(__half2*)(g_SelfM + ((size_t)s * MM + r0) * OO + c)
                        = __floats2half2_rn(v0.x, v0.y);
                    *(__half2*)(g_SelfM + ((size_t)s * MM + r0 + 8) * OO + c)
                        = __floats2half2_rn(v1.x, v1.y);
                }
            }
        }
    } else {
#pragma unroll
        for (int mf = 0; mf < 2; mf++) {
            int r0 = row0 + wm * 32 + mf * 16 + (lane >> 2);
#pragma unroll
            for (int j = 0; j < 8; j++) {
                int c = col0 + j * 8 + (lane & 3) * 2;
                *(__half2*)(g_FN + ((size_t)s * NN + r0) * OO + c)
                    = __floats2half2_rn(C[mf][j][0], C[mf][j][1]);
                *(__half2*)(g_FN + ((size_t)s * NN + r0 + 8) * OO + c)
                    = __floats2half2_rn(C[mf][j][2], C[mf][j][3]);
            }
        }
    }
#undef LOAD_TILE
#undef STORE_TILE
#undef COMPUTE_TILE
}

// ---------------- scatter worker (grid-stride over edges) ----------------
__device__ __forceinline__ void scatter_work(
    int chunk, const int* __restrict__ e_src, const int* __restrict__ e_dst)
{
    const int stride = SCAT_BLKS * 256;
    for (int e = chunk * 256 + threadIdx.x; e < NEDGES; e += stride) {
        int blk = e / EE;
        int row = c_blkoff[blk] + __ldg(e_dst + e);
        int pos = atomicAdd(&g_cur[row], 1);
        g_sorted_src[pos] = __ldg(e_src + e);
    }
}

// ---------------- F2: fused GEMM + scatter (dispatch-interleaved 2:1) ----------------
__global__ __launch_bounds__(256, 2) void gemm_scatter(
    const float* __restrict__ feats, const float* __restrict__ Ws,
    const float* __restrict__ Wn, const float* __restrict__ bias,
    float* __restrict__ out,
    const int* __restrict__ e_src, const int* __restrict__ e_dst)
{
    __shared__ unsigned As[BM][AS_STRIDE];
    __shared__ unsigned Bs[BK][BS_STRIDE];

    const int bx = blockIdx.x;
    const int p  = bx % 3;
    const int g3 = bx / 3;
    if (p < 2) {
        gemm_tile(g3 * 2 + p, feats, Ws, Wn, bias, out, As, Bs);
    } else {
        scatter_work(g3, e_src, e_dst);
    }
}

// ---------------- Sort pipeline ----------------
__global__ __launch_bounds__(256) void hist_kernel(const int* __restrict__ e_dst)
{
    int e = blockIdx.x * 256 + threadIdx.x;
    int blk = e / EE;
    int row = c_blkoff[blk] + __ldg(e_dst + e);
    atomicAdd(&g_cnt[row], 1);
}

__global__ __launch_bounds__(1024) void scan1_kernel()
{
    __shared__ int sm[1024];
    int tid = threadIdx.x;
    int i = blockIdx.x * 1024 + tid;
    int v = g_cnt[i];
    sm[tid] = v;
    __syncthreads();
    for (int ofs = 1; ofs < 1024; ofs <<= 1) {
        int t = (tid >= ofs) ? sm[tid - ofs] : 0;
        __syncthreads();
        sm[tid] += t;
        __syncthreads();
    }
    g_off[i] = sm[tid] - v;
    if (tid == 1023) g_part[blockIdx.x] = sm[1023];
}

__global__ __launch_bounds__(1024) void scan2_kernel()
{
    __shared__ int sm[1024];
    int tid = threadIdx.x;
    int v = (tid < 640) ? g_part[tid] : 0;
    sm[tid] = v;
    __syncthreads();
    for (int ofs = 1; ofs < 1024; ofs <<= 1) {
        int t = (tid >= ofs) ? sm[tid - ofs] : 0;
        __syncthreads();
        sm[tid] += t;
        __syncthreads();
    }
    if (tid < 640) g_part[tid] = sm[tid] - v;
}

__global__ __launch_bounds__(1024) void scan3_kernel()
{
    int i = blockIdx.x * 1024 + threadIdx.x;
    int o = g_off[i] + g_part[blockIdx.x];
    g_off[i] = o;
    g_cur[i] = o;
}

// ---------------- Phase B+C fused: warp per destination row, fp16 gather ----------------
__device__ __forceinline__ void acc_add(float4& acc, uint2 raw) {
    float2 f0 = __half22float2(*(__half2*)&raw.x);
    float2 f1 = __half22float2(*(__half2*)&raw.y);
    acc.x += f0.x; acc.y += f0.y; acc.z += f1.x; acc.w += f1.y;
}

__global__ __launch_bounds__(256) void agg_combine(
    float* __restrict__ out, const int* __restrict__ merge)
{
    const int lane = threadIdx.x & 31;
    const int r = blockIdx.x * 8 + (threadIdx.x >> 5);

    int blk = 0;
#pragma unroll
    for (int k = 1; k < 16; k++)
        if (r >= c_blkoff[k]) blk = k;
    const int s = blk >> 2, d = blk & 3;
    const int lrow = r - c_blkoff[blk];

    const int base = g_off[r];
    const int deg  = g_cnt[r];
    const uint2* FNs = (const uint2*)(g_FN + (size_t)s * NN * OO);

    float4 acc = make_float4(0.f, 0.f, 0.f, 0.f);
    for (int i0 = 0; i0 < deg; i0 += 32) {
        int mi = i0 + lane;
        int msrc = (mi < deg) ? __ldg(g_sorted_src + base + mi) : 0;
        int cnt = min(32, deg - i0);
        for (int j = 0; j < cnt; j++) {
            int src = __shfl_sync(0xffffffffu, msrc, j);
            uint2 raw = __ldg(FNs + (size_t)src * 32 + lane);
            acc_add(acc, raw);
        }
    }

    const float invd = (deg > 0) ? (1.0f / (float)deg) : 0.0f;

    if (s == d) {
        if (deg == 0) return;
        float* op = out + ((size_t)d * NN + lrow) * OO + lane * 4;
        asm volatile("red.global.add.v4.f32 [%0], {%1,%2,%3,%4};"
                     :: "l"(op), "f"(acc.x * invd), "f"(acc.y * invd),
                        "f"(acc.z * invd), "f"(acc.w * invd) : "memory");
    } else {
        uint2 smr = *((const uint2*)(g_SelfM + ((size_t)s * MM + lrow) * OO) + lane);
        float2 s0 = __half22float2(*(__half2*)&smr.x);
        float2 s1 = __half22float2(*(__half2*)&smr.y);
        float4 v;
        v.x = fmaf(acc.x, invd, s0.x);
        v.y = fmaf(acc.y, invd, s0.y);
        v.z = fmaf(acc.z, invd, s1.x);
        v.w = fmaf(acc.w, invd, s1.y);
        int tgt = __ldg(merge + (size_t)blk * MM + lrow);
        float* op = out + ((size_t)d * NN + tgt) * OO + lane * 4;
        asm volatile("red.global.add.v4.f32 [%0], {%1,%2,%3,%4};"
                     :: "l"(op), "f"(v.x), "f"(v.y), "f"(v.z), "f"(v.w) : "memory");
    }
}

// ---------------- launch ----------------
extern "C" void kernel_launch(void* const* d_in, const int* in_sizes, int n_in,
                              void* d_out, int out_size)
{
    const float* feats  = (const float*)d_in[0];   // [P,N,D]
    const float* Wself  = (const float*)d_in[1];   // [P,D,O]
    const float* Wneigh = (const float*)d_in[2];   // [P,D,O]
    const float* bias   = (const float*)d_in[3];   // [P,O]
    const int*   e_src  = (const int*)d_in[4];     // [P,P,E]
    const int*   e_dst  = (const int*)d_in[5];     // [P,P,E]
    const int*   merge  = (const int*)d_in[6];     // [P,P,M]
    float* out = (float*)d_out;                    // [P,N,O]

    void* cntPtr = nullptr; cudaGetSymbolAddress(&cntPtr, g_cnt);
    cudaMemsetAsync(cntPtr, 0, sizeof(int) * (size_t)TOTAL_ROWS, 0);

    hist_kernel<<<NEDGES / 256, 256>>>(e_dst);
    scan1_kernel<<<TOTAL_ROWS / 1024, 1024>>>();
    scan2_kernel<<<1, 1024>>>();
    scan3_kernel<<<TOTAL_ROWS / 1024, 1024>>>();

    gemm_scatter<<<F2_GRID, 256>>>(feats, Wself, Wneigh, bias, out, e_src, e_dst);

    agg_combine<<<TOTAL_ROWS / 8, 256>>>(out, merge);
}

// round 8
// speedup vs baseline: 1.0686x; 1.0430x over previous
#include <cuda_runtime.h>
#include <cuda_fp16.h>

#define PP 4
#define NN 65536
#define DD 128
#define OO 128
#define EE 500000
#define MM 32768
#define TOTAL_ROWS 655360   // 4*N + 12*M
#define NEDGES (16 * EE)    // 8,000,000

#define BM 128
#define BK 32
#define AS_STRIDE 36
#define BS_STRIDE 136

#define SCAT_BLKS  2048
#define F2_GRID    6144       // 3 * 2048, pattern [g,g,s]

// ---------------- scratch ----------------
__device__ __half g_FN[(size_t)PP * NN * OO];        // feats @ W_neigh, fp16 (67 MB)
__device__ __half g_SelfM[(size_t)PP * MM * OO];     // (feats@W_self + b) rows [0,M), fp16 (33 MB)
__device__ int   g_cnt[TOTAL_ROWS];
__device__ int   g_off[TOTAL_ROWS];
__device__ int   g_cur[TOTAL_ROWS];
__device__ int   g_part[1024];
__device__ unsigned short g_sorted_src[NEDGES];      // src ids (<65536) sorted by dst row (16 MB)

__constant__ int c_blkoff[17] = {
    0,      65536,  98304,  131072,
    163840, 196608, 262144, 294912,
    327680, 360448, 393216, 458752,
    491520, 524288, 557056, 589824, 655360};

__device__ __forceinline__ unsigned f2tf32(float v) {
    unsigned r;
    asm("cvt.rna.tf32.f32 %0, %1;" : "=r"(r) : "f"(v));
    return r;
}

// ---------------- GEMM tile worker (R5 body: non-pipelined tf32 MMA) ----------------
__device__ __forceinline__ void gemm_tile(
    int tileId,
    const float* __restrict__ feats, const float* __restrict__ Ws,
    const float* __restrict__ Wn, const float* __restrict__ bias,
    float* __restrict__ out,
    unsigned (*As)[AS_STRIDE], unsigned (*Bs)[BS_STRIDE])
{
    const int x  = tileId & 511;
    const int yz = tileId >> 9;
    const bool isSelf = (yz & 1) == 0;
    const int s  = yz >> 1;
    const int row0 = x * BM;

    const float* A = feats + (size_t)s * NN * DD;
    const float* B = (isSelf ? Ws : Wn) + (size_t)s * DD * OO;

    const int t    = threadIdx.x;
    const int lane = t & 31;
    const int wid  = t >> 5;
    const int wm   = wid >> 1;
    const int wn   = wid & 1;

    float C[2][8][4];
#pragma unroll
    for (int mf = 0; mf < 2; mf++)
#pragma unroll
        for (int j = 0; j < 8; j++)
#pragma unroll
            for (int q = 0; q < 4; q++) C[mf][j][q] = 0.0f;

    for (int kt = 0; kt < DD; kt += BK) {
#pragma unroll
        for (int q = 0; q < 4; q++) {
            int i  = t + 256 * q;
            int r  = i >> 3;
            int k0 = (i & 7) * 4;
            float4 v = *(const float4*)(A + (size_t)(row0 + r) * DD + kt + k0);
            *(uint4*)&As[r][k0] = make_uint4(f2tf32(v.x), f2tf32(v.y),
                                             f2tf32(v.z), f2tf32(v.w));
        }
#pragma unroll
        for (int q = 0; q < 4; q++) {
            int i  = t + 256 * q;
            int k  = i >> 5;
            int n0 = (i & 31) * 4;
            float4 v = *(const float4*)(B + (size_t)(kt + k) * OO + n0);
            *(uint4*)&Bs[k][n0] = make_uint4(f2tf32(v.x), f2tf32(v.y),
                                             f2tf32(v.z), f2tf32(v.w));
        }
        __syncthreads();

#pragma unroll
        for (int kk = 0; kk < BK; kk += 8) {
            unsigned a[2][4];
#pragma unroll
            for (int mf = 0; mf < 2; mf++) {
                int r = wm * 32 + mf * 16 + (lane >> 2);
                int kc = kk + (lane & 3);
                a[mf][0] = As[r][kc];
                a[mf][1] = As[r + 8][kc];
                a[mf][2] = As[r][kc + 4];
                a[mf][3] = As[r + 8][kc + 4];
            }
#pragma unroll
            for (int j = 0; j < 8; j++) {
                int n = wn * 64 + j * 8 + (lane >> 2);
                unsigned b0 = Bs[kk + (lane & 3)][n];
                unsigned b1 = Bs[kk + (lane & 3) + 4][n];
#pragma unroll
                for (int mf = 0; mf < 2; mf++) {
                    asm("mma.sync.aligned.m16n8k8.row.col.f32.tf32.tf32.f32 "
                        "{%0,%1,%2,%3}, {%4,%5,%6,%7}, {%8,%9}, {%0,%1,%2,%3};"
                        : "+f"(C[mf][j][0]), "+f"(C[mf][j][1]),
                          "+f"(C[mf][j][2]), "+f"(C[mf][j][3])
                        : "r"(a[mf][0]), "r"(a[mf][1]),
                          "r"(a[mf][2]), "r"(a[mf][3]),
                          "r"(b0), "r"(b1));
                }
            }
        }
        __syncthreads();
    }

    const int col0 = wn * 64;
    if (isSelf) {
#pragma unroll
        for (int mf = 0; mf < 2; mf++) {
            int r0 = row0 + wm * 32 + mf * 16 + (lane >> 2);
#pragma unroll
            for (int j = 0; j < 8; j++) {
                int c = col0 + j * 8 + (lane & 3) * 2;
                float b0v = __ldg(bias + s * OO + c);
                float b1v = __ldg(bias + s * OO + c + 1);
                float2 v0 = make_float2(C[mf][j][0] + b0v, C[mf][j][1] + b1v);
                float2 v1 = make_float2(C[mf][j][2] + b0v, C[mf][j][3] + b1v);
                *(float2*)(out + ((size_t)s * NN + r0) * OO + c)     = v0;
                *(float2*)(out + ((size_t)s * NN + r0 + 8) * OO + c) = v1;
                if (r0 < MM) {
                    *(__half2*)(g_SelfM + ((size_t)s * MM + r0) * OO + c)
                        = __floats2half2_rn(v0.x, v0.y);
                    *(__half2*)(g_SelfM + ((size_t)s * MM + r0 + 8) * OO + c)
                        = __floats2half2_rn(v1.x, v1.y);
                }
            }
        }
    } else {
#pragma unroll
        for (int mf = 0; mf < 2; mf++) {
            int r0 = row0 + wm * 32 + mf * 16 + (lane >> 2);
#pragma unroll
            for (int j = 0; j < 8; j++) {
                int c = col0 + j * 8 + (lane & 3) * 2;
                *(__half2*)(g_FN + ((size_t)s * NN + r0) * OO + c)
                    = __floats2half2_rn(C[mf][j][0], C[mf][j][1]);
                *(__half2*)(g_FN + ((size_t)s * NN + r0 + 8) * OO + c)
                    = __floats2half2_rn(C[mf][j][2], C[mf][j][3]);
            }
        }
    }
}

// ---------------- scatter worker (grid-stride over edges) ----------------
__device__ __forceinline__ void scatter_work(
    int chunk, const int* __restrict__ e_src, const int* __restrict__ e_dst)
{
    const int stride = SCAT_BLKS * 256;
    for (int e = chunk * 256 + threadIdx.x; e < NEDGES; e += stride) {
        int blk = e / EE;
        int row = c_blkoff[blk] + __ldg(e_dst + e);
        int pos = atomicAdd(&g_cur[row], 1);
        g_sorted_src[pos] = (unsigned short)__ldg(e_src + e);
    }
}

// ---------------- F2: fused GEMM + scatter (dispatch-interleaved 2:1) ----------------
__global__ __launch_bounds__(256, 2) void gemm_scatter(
    const float* __restrict__ feats, const float* __restrict__ Ws,
    const float* __restrict__ Wn, const float* __restrict__ bias,
    float* __restrict__ out,
    const int* __restrict__ e_src, const int* __restrict__ e_dst)
{
    __shared__ unsigned As[BM][AS_STRIDE];
    __shared__ unsigned Bs[BK][BS_STRIDE];

    const int bx = blockIdx.x;
    const int p  = bx % 3;
    const int g3 = bx / 3;
    if (p < 2) {
        gemm_tile(g3 * 2 + p, feats, Ws, Wn, bias, out, As, Bs);
    } else {
        scatter_work(g3, e_src, e_dst);
    }
}

// ---------------- Sort pipeline ----------------
__global__ __launch_bounds__(256) void hist_kernel(const int* __restrict__ e_dst)
{
    int e = blockIdx.x * 256 + threadIdx.x;
    int blk = e / EE;
    int row = c_blkoff[blk] + __ldg(e_dst + e);
    atomicAdd(&g_cnt[row], 1);
}

__global__ __launch_bounds__(1024) void scan1_kernel()
{
    __shared__ int sm[1024];
    int tid = threadIdx.x;
    int i = blockIdx.x * 1024 + tid;
    int v = g_cnt[i];
    sm[tid] = v;
    __syncthreads();
    for (int ofs = 1; ofs < 1024; ofs <<= 1) {
        int t = (tid >= ofs) ? sm[tid - ofs] : 0;
        __syncthreads();
        sm[tid] += t;
        __syncthreads();
    }
    g_off[i] = sm[tid] - v;
    if (tid == 1023) g_part[blockIdx.x] = sm[1023];
}

__global__ __launch_bounds__(1024) void scan2_kernel()
{
    __shared__ int sm[1024];
    int tid = threadIdx.x;
    int v = (tid < 640) ? g_part[tid] : 0;
    sm[tid] = v;
    __syncthreads();
    for (int ofs = 1; ofs < 1024; ofs <<= 1) {
        int t = (tid >= ofs) ? sm[tid - ofs] : 0;
        __syncthreads();
        sm[tid] += t;
        __syncthreads();
    }
    if (tid < 640) g_part[tid] = sm[tid] - v;
}

__global__ __launch_bounds__(1024) void scan3_kernel()
{
    int i = blockIdx.x * 1024 + threadIdx.x;
    int o = g_off[i] + g_part[blockIdx.x];
    g_off[i] = o;
    g_cur[i] = o;
}

// ---------------- Phase B+C fused: warp per destination row, fp16 gather ----------------
__device__ __forceinline__ void acc_add(float4& acc, uint2 raw) {
    float2 f0 = __half22float2(*(__half2*)&raw.x);
    float2 f1 = __half22float2(*(__half2*)&raw.y);
    acc.x += f0.x; acc.y += f0.y; acc.z += f1.x; acc.w += f1.y;
}

__global__ __launch_bounds__(256) void agg_combine(
    float* __restrict__ out, const int* __restrict__ merge)
{
    const int lane = threadIdx.x & 31;
    const int r = blockIdx.x * 8 + (threadIdx.x >> 5);

    int blk = 0;
#pragma unroll
    for (int k = 1; k < 16; k++)
        if (r >= c_blkoff[k]) blk = k;
    const int s = blk >> 2, d = blk & 3;
    const int lrow = r - c_blkoff[blk];

    const int base = g_off[r];
    const int deg  = g_cnt[r];
    const uint2* FNs = (const uint2*)(g_FN + (size_t)s * NN * OO);

    float4 acc = make_float4(0.f, 0.f, 0.f, 0.f);
    for (int i0 = 0; i0 < deg; i0 += 32) {
        int mi = i0 + lane;
        int msrc = (mi < deg) ? (int)g_sorted_src[base + mi] : 0;
        int cnt = min(32, deg - i0);
        for (int j = 0; j < cnt; j++) {
            int src = __shfl_sync(0xffffffffu, msrc, j);
            uint2 raw = __ldg(FNs + (size_t)src * 32 + lane);
            acc_add(acc, raw);
        }
    }

    const float invd = (deg > 0) ? (1.0f / (float)deg) : 0.0f;

    if (s == d) {
        if (deg == 0) return;
        float* op = out + ((size_t)d * NN + lrow) * OO + lane * 4;
        asm volatile("red.global.add.v4.f32 [%0], {%1,%2,%3,%4};"
                     :: "l"(op), "f"(acc.x * invd), "f"(acc.y * invd),
                        "f"(acc.z * invd), "f"(acc.w * invd) : "memory");
    } else {
        uint2 smr = *((const uint2*)(g_SelfM + ((size_t)s * MM + lrow) * OO) + lane);
        float2 s0 = __half22float2(*(__half2*)&smr.x);
        float2 s1 = __half22float2(*(__half2*)&smr.y);
        float4 v;
        v.x = fmaf(acc.x, invd, s0.x);
        v.y = fmaf(acc.y, invd, s0.y);
        v.z = fmaf(acc.z, invd, s1.x);
        v.w = fmaf(acc.w, invd, s1.y);
        int tgt = __ldg(merge + (size_t)blk * MM + lrow);
        float* op = out + ((size_t)d * NN + tgt) * OO + lane * 4;
        asm volatile("red.global.add.v4.f32 [%0], {%1,%2,%3,%4};"
                     :: "l"(op), "f"(v.x), "f"(v.y), "f"(v.z), "f"(v.w) : "memory");
    }
}

// ---------------- launch ----------------
extern "C" void kernel_launch(void* const* d_in, const int* in_sizes, int n_in,
                              void* d_out, int out_size)
{
    const float* feats  = (const float*)d_in[0];   // [P,N,D]
    const float* Wself  = (const float*)d_in[1];   // [P,D,O]
    const float* Wneigh = (const float*)d_in[2];   // [P,D,O]
    const float* bias   = (const float*)d_in[3];   // [P,O]
    const int*   e_src  = (const int*)d_in[4];     // [P,P,E]
    const int*   e_dst  = (const int*)d_in[5];     // [P,P,E]
    const int*   merge  = (const int*)d_in[6];     // [P,P,M]
    float* out = (float*)d_out;                    // [P,N,O]

    void* cntPtr = nullptr; cudaGetSymbolAddress(&cntPtr, g_cnt);
    cudaMemsetAsync(cntPtr, 0, sizeof(int) * (size_t)TOTAL_ROWS, 0);

    hist_kernel<<<NEDGES / 256, 256>>>(e_dst);
    scan1_kernel<<<TOTAL_ROWS / 1024, 1024>>>();
    scan2_kernel<<<1, 1024>>>();
    scan3_kernel<<<TOTAL_ROWS / 1024, 1024>>>();

    gemm_scatter<<<F2_GRID, 256>>>(feats, Wself, Wneigh, bias, out, e_src, e_dst);

    agg_combine<<<TOTAL_ROWS / 8, 256>>>(out, merge);
}